// round 12
// baseline (speedup 1.0000x reference)
#include <cuda_runtime.h>

// Persistent-kernel TV denoiser (Chambolle-Pock, RHO-relaxed), single launch.
// 592 blocks (= 148 SMs x 4 CTAs) x 128 threads; float4 columns; 6/7-row
// in-image stripes. Each iteration: bulk-stage stripe state global->smem
// (independent loads, high MLP), one sync, then compute from smem (LDS
// latency) and stream results to global. One grid barrier per iteration;
// deterministic redundant convergence decision (R7 scheme).

#define WW 512
#define HH 512
#define IMG (HH*WW)
#define BATCH 8
#define NTOT (BATCH*IMG)
#define NTHR 128
#define NWARP (NTHR/32)
#define BPI 74                   // blocks per image
#define NBLK (BATCH*BPI)         // 592 = 148*4, all co-resident
#define NB7 68                   // stripes 0..67: 7 rows; 68..73: 6 rows

#define TAUc     0.01f
#define INV1PTAU (1.0f/1.01f)
#define SIGMAc   12.5f
#define RHOc     1.99f
#define HRHOc    0.995f          /* RHO/2 */
#define THSc     0.1f
#define THS2c    0.01f           /* THS^2 */
#define CRITc    1e-5f
#define NITERc   40

// smem layout (rows of WW floats): sx2: 8 rows, su0: 9 rows, su1: 8 rows
#define SX2_OFF 0
#define SU0_OFF (8*WW)
#define SU1_OFF (17*WW)
#define SMEM_FLOATS (25*WW)      // 51200 B

__device__ float g_x [2][NTOT];
__device__ float g_u0[2][NTOT];
__device__ float g_u1[2][NTOT];
__device__ float g_pnum[2][NBLK];
__device__ float g_pden[2][NBLK];
__device__ unsigned int          g_count = 0;
__device__ volatile unsigned int g_gen   = 0;

__device__ __forceinline__ void grid_barrier()
{
    __threadfence();
    __syncthreads();
    if (threadIdx.x == 0) {
        unsigned int gen = g_gen;
        if (atomicInc(&g_count, NBLK - 1u) == NBLK - 1u) {
            g_gen = gen + 1u;
        } else {
            while (g_gen == gen) __nanosleep(32);
        }
    }
    __syncthreads();
    __threadfence();
}

// z = 2x - x2 for this thread's 4 columns at stripe-row rr, plus the lane-31
// fixup column (c+4). All state from smem; y from global (yg = row base + c).
// su0 slot k holds image row i0+k-1 (slot 0 = top halo).
__device__ __forceinline__ void row_z_s(
    const float* sx2, const float* su0, const float* su1,
    const float* __restrict__ yg,
    int rr, int c, int tid, int lane, bool cfixOK, bool nl,
    float4& u0c, float4& u1c, float4& x2c, float4& z, float& zf)
{
    u0c = *(const float4*)(su0 + (rr + 1) * WW + c);
    u1c = *(const float4*)(su1 + rr * WW + c);
    x2c = *(const float4*)(sx2 + rr * WW + c);
    float4 u0p = *(const float4*)(su0 + rr * WW + c);
    float4 yc  = *(const float4*)(yg);

    float u1left = __shfl_up_sync(0xffffffffu, u1c.w, 1);
    if (lane == 0) u1left = (tid > 0) ? su1[rr * WW + c - 1] : 0.f;

    float u0x = nl ? u0c.x : 0.f;
    float u0y = nl ? u0c.y : 0.f;
    float u0z = nl ? u0c.z : 0.f;
    float u0w = nl ? u0c.w : 0.f;
    float u1w = (tid == NTHR - 1) ? 0.f : u1c.w;   // col 511: no right diff

    float ax = u0p.x + u1left - u0x - u1c.x;
    float ay = u0p.y + u1c.x  - u0y - u1c.y;
    float az = u0p.z + u1c.y  - u0z - u1c.z;
    float aw = u0p.w + u1c.z  - u0w - u1w;

    float x0 = fmaf(TAUc, yc.x - ax, x2c.x) * INV1PTAU;
    float x1 = fmaf(TAUc, yc.y - ay, x2c.y) * INV1PTAU;
    float x2 = fmaf(TAUc, yc.z - az, x2c.z) * INV1PTAU;
    float x3 = fmaf(TAUc, yc.w - aw, x2c.w) * INV1PTAU;
    z.x = 2.f * x0 - x2c.x;
    z.y = 2.f * x1 - x2c.y;
    z.z = 2.f * x2 - x2c.z;
    z.w = 2.f * x3 - x2c.w;

    zf = 0.f;
    if (cfixOK) {                       // lane 31 (not tid 127): column c+4
        float u0f  = su0[(rr + 1) * WW + c + 4];
        float u0pf = su0[rr * WW + c + 4];
        float u1f  = su1[rr * WW + c + 4];
        float x2f  = sx2[rr * WW + c + 4];
        float yf   = yg[4];
        float u0fx = nl ? u0f : 0.f;
        float af = u0pf + u1c.w - u0fx - u1f;
        float xf = fmaf(TAUc, yf - af, x2f) * INV1PTAU;
        zf = 2.f * xf - x2f;
    }
}

template<int NR>
__device__ __forceinline__ void do_rows(
    float* sx2, float* su0, float* su1,
    const float* __restrict__ xin, const float* __restrict__ u0in,
    const float* __restrict__ u1in, const float* __restrict__ yv,
    float* __restrict__ xout, float* __restrict__ u0out,
    float* __restrict__ u1out,
    int g0, int i0, bool isTop, bool notBottom, int tid, int lane, bool cfixOK,
    float& num, float& den)
{
    const int c = 4 * tid;
    const float4 zz = make_float4(0.f, 0.f, 0.f, 0.f);

    // ---- stage stripe state into smem (independent loads, high MLP) ----
    #pragma unroll
    for (int r = 0; r < NR; r++) {
        *(float4*)(sx2 + r * WW + c)       = *(const float4*)(xin  + g0 + r * WW);
        *(float4*)(su0 + (r + 1) * WW + c) = *(const float4*)(u0in + g0 + r * WW);
        *(float4*)(su1 + r * WW + c)       = *(const float4*)(u1in + g0 + r * WW);
    }
    *(float4*)(su0 + c) = isTop ? zz : *(const float4*)(u0in + g0 - WW);
    if (notBottom) {                    // bottom halo row i0+NR
        *(float4*)(sx2 + NR * WW + c)       = *(const float4*)(xin  + g0 + NR * WW);
        *(float4*)(su0 + (NR + 1) * WW + c) = *(const float4*)(u0in + g0 + NR * WW);
        *(float4*)(su1 + NR * WW + c)       = *(const float4*)(u1in + g0 + NR * WW);
    }
    __syncthreads();

    // ---- compute (prologue: z at stripe-row 0; i0 <= 506 so nl true) ----
    float4 u0c, u1c, x2c, z;
    float zfc;
    row_z_s(sx2, su0, su1, yv + g0, 0, c, tid, lane, cfixOK, true,
            u0c, u1c, x2c, z, zfc);

    int g = g0;
    #pragma unroll
    for (int r = 0; r < NR; r++) {
        const bool nl = (r < NR - 1) || notBottom;

        float4 u0N = zz, u1N = zz, x2N = zz, zN = zz;
        float zfN = 0.f;
        if (nl) {                                    // block-uniform
            const bool nlN = (i0 + r + 1) != (HH - 1);
            row_z_s(sx2, su0, su1, yv + g + WW, r + 1, c, tid, lane, cfixOK,
                    nlN, u0N, u1N, x2N, zN, zfN);
        }

        float zsh = __shfl_down_sync(0xffffffffu, z.x, 1);
        float zr  = (lane == 31) ? zfc : zsh;
        float dwx = z.y - z.x;
        float dwy = z.z - z.y;
        float dwz = z.w - z.z;
        float dww = (tid == NTHR - 1) ? 0.f : (zr - z.w);

        float dhx = nl ? (zN.x - z.x) : 0.f;
        float dhy = nl ? (zN.y - z.y) : 0.f;
        float dhz = nl ? (zN.z - z.z) : 0.f;
        float dhw = nl ? (zN.w - z.w) : 0.f;

        float v0x = fmaf(SIGMAc, dhx, u0c.x);
        float v0y = fmaf(SIGMAc, dhy, u0c.y);
        float v0z = fmaf(SIGMAc, dhz, u0c.z);
        float v0w = fmaf(SIGMAc, dhw, u0c.w);
        float v1x = fmaf(SIGMAc, dwx, u1c.x);
        float v1y = fmaf(SIGMAc, dwy, u1c.y);
        float v1z = fmaf(SIGMAc, dwz, u1c.z);
        float v1w = fmaf(SIGMAc, dww, u1c.w);

        float m2x = fmaf(v0x, v0x, v1x * v1x);
        float m2y = fmaf(v0y, v0y, v1y * v1y);
        float m2z = fmaf(v0z, v0z, v1z * v1z);
        float m2w = fmaf(v0w, v0w, v1w * v1w);
        float scx = (m2x > THS2c) ? (THSc * rsqrtf(m2x)) : 1.f;
        float scy = (m2y > THS2c) ? (THSc * rsqrtf(m2y)) : 1.f;
        float scz = (m2z > THS2c) ? (THSc * rsqrtf(m2z)) : 1.f;
        float scw = (m2w > THS2c) ? (THSc * rsqrtf(m2w)) : 1.f;

        float4 xn, u0n, u1n;
        xn.x  = fmaf(HRHOc, z.x - x2c.x, x2c.x);
        xn.y  = fmaf(HRHOc, z.y - x2c.y, x2c.y);
        xn.z  = fmaf(HRHOc, z.z - x2c.z, x2c.z);
        xn.w  = fmaf(HRHOc, z.w - x2c.w, x2c.w);
        u0n.x = fmaf(RHOc, fmaf(v0x, scx, -u0c.x), u0c.x);
        u0n.y = fmaf(RHOc, fmaf(v0y, scy, -u0c.y), u0c.y);
        u0n.z = fmaf(RHOc, fmaf(v0z, scz, -u0c.z), u0c.z);
        u0n.w = fmaf(RHOc, fmaf(v0w, scw, -u0c.w), u0c.w);
        u1n.x = fmaf(RHOc, fmaf(v1x, scx, -u1c.x), u1c.x);
        u1n.y = fmaf(RHOc, fmaf(v1y, scy, -u1c.y), u1c.y);
        u1n.z = fmaf(RHOc, fmaf(v1z, scz, -u1c.z), u1c.z);
        u1n.w = fmaf(RHOc, fmaf(v1w, scw, -u1c.w), u1c.w);

        *(float4*)(xout  + g) = xn;
        *(float4*)(u0out + g) = u0n;
        *(float4*)(u1out + g) = u1n;

        float d0 = xn.x - x2c.x, d1 = xn.y - x2c.y;
        float d2 = xn.z - x2c.z, d3 = xn.w - x2c.w;
        num = fmaf(d0, d0, num);  num = fmaf(d1, d1, num);
        num = fmaf(d2, d2, num);  num = fmaf(d3, d3, num);
        float e0 = xn.x + 1e-12f, e1 = xn.y + 1e-12f;
        float e2 = xn.z + 1e-12f, e3 = xn.w + 1e-12f;
        den = fmaf(e0, e0, den);  den = fmaf(e1, e1, den);
        den = fmaf(e2, e2, den);  den = fmaf(e3, e3, den);

        u0c = u0N; u1c = u1N; x2c = x2N;
        z = zN; zfc = zfN;
        g += WW;
    }
}

__global__ void __launch_bounds__(NTHR, 4)
tv_persistent(const float* __restrict__ yv, float* __restrict__ out)
{
    extern __shared__ float dyn_smem[];
    float* sx2 = dyn_smem + SX2_OFF;
    float* su0 = dyn_smem + SU0_OFF;
    float* su1 = dyn_smem + SU1_OFF;

    const int tid  = threadIdx.x;
    const int lane = tid & 31;
    const int wid  = tid >> 5;
    const int blk  = blockIdx.x;
    const bool cfixOK = (lane == 31) && (tid != NTHR - 1);

    const int b = blk / BPI;            // image
    const int s = blk - b * BPI;        // stripe within image (0..73)
    const int nrows = (s < NB7) ? 7 : 6;
    const int i0 = (s < NB7) ? (7 * s) : (7 * NB7 + 6 * (s - NB7));
    const bool isTop     = (s == 0);
    const bool notBottom = (s != BPI - 1);
    const int g0 = b * IMG + i0 * WW + 4 * tid;

    __shared__ float snum[NWARP], sden[NWARP];
    __shared__ float sdec;

    // ---- init own stripe: x2 = y, u = 0 ----
    {
        int gg = g0;
        const float4 zz = make_float4(0.f, 0.f, 0.f, 0.f);
        for (int r = 0; r < nrows; r++, gg += WW) {
            *(float4*)(g_x [0] + gg) = *(const float4*)(yv + gg);
            *(float4*)(g_u0[0] + gg) = zz;
            *(float4*)(g_u1[0] + gg) = zz;
        }
    }
    grid_barrier();

    int executed = NITERc;

    for (int t = 0; t < NITERc; t++) {
        const int p = t & 1;
        const float* __restrict__ xin  = g_x [p];
        const float* __restrict__ u0in = g_u0[p];
        const float* __restrict__ u1in = g_u1[p];
        float* __restrict__ xout  = g_x [p ^ 1];
        float* __restrict__ u0out = g_u0[p ^ 1];
        float* __restrict__ u1out = g_u1[p ^ 1];

        float num = 0.f, den = 0.f;
        if (nrows == 7)
            do_rows<7>(sx2, su0, su1, xin, u0in, u1in, yv, xout, u0out, u1out,
                       g0, i0, isTop, notBottom, tid, lane, cfixOK, num, den);
        else
            do_rows<6>(sx2, su0, su1, xin, u0in, u1in, yv, xout, u0out, u1out,
                       g0, i0, isTop, notBottom, tid, lane, cfixOK, num, den);

        // -- publish convergence partials (needed from t >= 2) --
        if (t >= 2) {
            #pragma unroll
            for (int o = 16; o; o >>= 1) {
                num += __shfl_down_sync(0xffffffffu, num, o);
                den += __shfl_down_sync(0xffffffffu, den, o);
            }
            if (lane == 0) { snum[wid] = num; sden[wid] = den; }
            __syncthreads();
            if (tid == 0) {
                float n2 = 0.f, d2 = 0.f;
                #pragma unroll
                for (int w = 0; w < NWARP; w++) { n2 += snum[w]; d2 += sden[w]; }
                g_pnum[p][blk] = n2;
                g_pden[p][blk] = d2;
            }
        }

        grid_barrier();

        if (t >= 2) {
            // every block redundantly reduces the 592 partials in an identical
            // fixed order -> identical float result -> identical decision.
            float n2 = 0.f, d2 = 0.f;
            #pragma unroll
            for (int k = 0; k < (NBLK + NTHR - 1) / NTHR; k++) {
                int idx = tid + k * NTHR;
                if (idx < NBLK) { n2 += g_pnum[p][idx]; d2 += g_pden[p][idx]; }
            }
            #pragma unroll
            for (int o = 16; o; o >>= 1) {
                n2 += __shfl_down_sync(0xffffffffu, n2, o);
                d2 += __shfl_down_sync(0xffffffffu, d2, o);
            }
            if (lane == 0) { snum[wid] = n2; sden[wid] = d2; }
            __syncthreads();
            if (tid == 0) {
                float N = 0.f, D = 0.f;
                #pragma unroll
                for (int w = 0; w < NWARP; w++) { N += snum[w]; D += sden[w]; }
                sdec = sqrtf(N) / sqrtf(D);
            }
            __syncthreads();
            if (sdec < CRITc) { executed = t + 1; break; }
            __syncthreads();   // protect snum/sden reuse next iteration
        }
    }

    // ---- write own stripe from the buffer holding the final state ----
    const float* __restrict__ src = g_x[executed & 1];
    int gg = g0;
    for (int r = 0; r < nrows; r++, gg += WW)
        *(float4*)(out + gg) = *(const float4*)(src + gg);
}

extern "C" void kernel_launch(void* const* d_in, const int* in_sizes, int n_in,
                              void* d_out, int out_size) {
    const float* y = (const float*)d_in[0];
    float* out = (float*)d_out;
    const int smem_bytes = SMEM_FLOATS * sizeof(float);   // 51200 B dynamic
    cudaFuncSetAttribute(tv_persistent,
                         cudaFuncAttributeMaxDynamicSharedMemorySize,
                         smem_bytes + 1024);
    tv_persistent<<<NBLK, NTHR, smem_bytes>>>(y, out);
}

// round 13
// speedup vs baseline: 1.3568x; 1.3568x over previous
#include <cuda_runtime.h>

// Persistent-kernel TV denoiser (Chambolle-Pock, RHO-relaxed), single launch.
// TEMPORAL BLOCKING: 2 iterations per grid barrier. Phase A computes step t
// for the stripe +1 halo row each side (reads global parity p) into SMEM;
// Phase B computes step t+1 from SMEM and writes global parity p^1.
// 592 blocks (=148 SMs x 4 CTAs) x 128 threads, float4 columns.

#define WW 512
#define HH 512
#define IMG (HH*WW)
#define BATCH 8
#define NTOT (BATCH*IMG)
#define NTHR 128
#define NWARP (NTHR/32)
#define BPI 74                   // blocks per image
#define NBLK (BATCH*BPI)         // 592 = 148*4, all co-resident
#define NB7 68                   // stripes 0..67: 7 rows; 68..73: 6 rows
#define NSUP 20                  // supersteps (2 iters each)

#define TAUc     0.01f
#define INV1PTAU (1.0f/1.01f)
#define SIGMAc   12.5f
#define RHOc     1.99f
#define HRHOc    0.995f
#define THSc     0.1f
#define THS2c    0.01f
#define CRITc    1e-5f
#define NITERc   40

// smem layout (rows of WW floats): sx2: 8 rows (rows i0..i0+NR),
// su0: 9 rows (rows i0-1..i0+NR), su1: 8 rows (rows i0..i0+NR)
#define SX2_OFF 0
#define SU0_OFF (8*WW)
#define SU1_OFF (17*WW)
#define SMEM_FLOATS (25*WW)      // 51200 B

__device__ float g_x [2][NTOT];
__device__ float g_u0[2][NTOT];
__device__ float g_u1[2][NTOT];
__device__ float g_pn1[2][NBLK], g_pd1[2][NBLK];
__device__ float g_pn2[2][NBLK], g_pd2[2][NBLK];
__device__ unsigned int          g_count = 0;
__device__ volatile unsigned int g_gen   = 0;

__device__ __forceinline__ void grid_barrier()
{
    __threadfence();
    __syncthreads();
    if (threadIdx.x == 0) {
        unsigned int gen = g_gen;
        if (atomicInc(&g_count, NBLK - 1u) == NBLK - 1u) {
            g_gen = gen + 1u;
        } else {
            while (g_gen == gen) __nanosleep(32);
        }
    }
    __syncthreads();
    __threadfence();
}

// ---- z from GLOBAL state (R7), with lane-31 fixup column c+4 ----
__device__ __forceinline__ void row_quad(
    const float* __restrict__ xin, const float* __restrict__ u0in,
    const float* __restrict__ u1in, const float* __restrict__ yv,
    int g, int tid, int lane, bool cfixOK, bool nl,
    float4 u0prev, float u0fixprev,
    float4& u0c, float4& u1c, float4& x2c,
    float4& z, float& zf, float& u0fc)
{
    u0c = *(const float4*)(u0in + g);
    u1c = *(const float4*)(u1in + g);
    x2c = *(const float4*)(xin  + g);
    float4 yc = *(const float4*)(yv + g);

    float u1left = __shfl_up_sync(0xffffffffu, u1c.w, 1);
    if (lane == 0) u1left = (tid > 0) ? u1in[g - 1] : 0.f;

    float u0x = nl ? u0c.x : 0.f;
    float u0y = nl ? u0c.y : 0.f;
    float u0z = nl ? u0c.z : 0.f;
    float u0w = nl ? u0c.w : 0.f;
    float u1w = (tid == NTHR - 1) ? 0.f : u1c.w;

    float ax = u0prev.x + u1left - u0x - u1c.x;
    float ay = u0prev.y + u1c.x  - u0y - u1c.y;
    float az = u0prev.z + u1c.y  - u0z - u1c.z;
    float aw = u0prev.w + u1c.z  - u0w - u1w;

    float x0 = fmaf(TAUc, yc.x - ax, x2c.x) * INV1PTAU;
    float x1 = fmaf(TAUc, yc.y - ay, x2c.y) * INV1PTAU;
    float x2 = fmaf(TAUc, yc.z - az, x2c.z) * INV1PTAU;
    float x3 = fmaf(TAUc, yc.w - aw, x2c.w) * INV1PTAU;
    z.x = 2.f * x0 - x2c.x;
    z.y = 2.f * x1 - x2c.y;
    z.z = 2.f * x2 - x2c.z;
    z.w = 2.f * x3 - x2c.w;

    zf = 0.f; u0fc = 0.f;
    if (cfixOK) {
        float u0f = u0in[g + 4];
        float u1f = u1in[g + 4];
        float x2f = xin [g + 4];
        float yf  = yv  [g + 4];
        float u0fx = nl ? u0f : 0.f;
        float af = u0fixprev + u1c.w - u0fx - u1f;
        float xf = fmaf(TAUc, yf - af, x2f) * INV1PTAU;
        zf = 2.f * xf - x2f;
        u0fc = u0f;
    }
}

// ---- z from SMEM state (R9). su0 slot k = image row i0+k-1. ----
__device__ __forceinline__ void row_z_s(
    const float* sx2, const float* su0, const float* su1,
    const float* __restrict__ yg,
    int rr, int c, int tid, int lane, bool cfixOK, bool nl,
    float4& u0c, float4& u1c, float4& x2c, float4& z, float& zf)
{
    u0c = *(const float4*)(su0 + (rr + 1) * WW + c);
    u1c = *(const float4*)(su1 + rr * WW + c);
    x2c = *(const float4*)(sx2 + rr * WW + c);
    float4 u0p = *(const float4*)(su0 + rr * WW + c);
    float4 yc  = *(const float4*)(yg);

    float u1left = __shfl_up_sync(0xffffffffu, u1c.w, 1);
    if (lane == 0) u1left = (tid > 0) ? su1[rr * WW + c - 1] : 0.f;

    float u0x = nl ? u0c.x : 0.f;
    float u0y = nl ? u0c.y : 0.f;
    float u0z = nl ? u0c.z : 0.f;
    float u0w = nl ? u0c.w : 0.f;
    float u1w = (tid == NTHR - 1) ? 0.f : u1c.w;

    float ax = u0p.x + u1left - u0x - u1c.x;
    float ay = u0p.y + u1c.x  - u0y - u1c.y;
    float az = u0p.z + u1c.y  - u0z - u1c.z;
    float aw = u0p.w + u1c.z  - u0w - u1w;

    float x0 = fmaf(TAUc, yc.x - ax, x2c.x) * INV1PTAU;
    float x1 = fmaf(TAUc, yc.y - ay, x2c.y) * INV1PTAU;
    float x2 = fmaf(TAUc, yc.z - az, x2c.z) * INV1PTAU;
    float x3 = fmaf(TAUc, yc.w - aw, x2c.w) * INV1PTAU;
    z.x = 2.f * x0 - x2c.x;
    z.y = 2.f * x1 - x2c.y;
    z.z = 2.f * x2 - x2c.z;
    z.w = 2.f * x3 - x2c.w;

    zf = 0.f;
    if (cfixOK) {
        float u0f  = su0[(rr + 1) * WW + c + 4];
        float u0pf = su0[rr * WW + c + 4];
        float u1f  = su1[rr * WW + c + 4];
        float x2f  = sx2[rr * WW + c + 4];
        float yf   = yg[4];
        float u0fx = nl ? u0f : 0.f;
        float af = u0pf + u1c.w - u0fx - u1f;
        float xf = fmaf(TAUc, yf - af, x2f) * INV1PTAU;
        zf = 2.f * xf - x2f;
    }
}

// prox + relax from (z, zN, state) -> (xn, u0n, u1n) + stats
#define FINALIZE(z, zN, zfc, u0c, u1c, x2c, nl, xn, u0n, u1n)                 \
    float zsh = __shfl_down_sync(0xffffffffu, (z).x, 1);                      \
    float zr  = (lane == 31) ? (zfc) : zsh;                                   \
    float dwx = (z).y - (z).x;                                                \
    float dwy = (z).z - (z).y;                                                \
    float dwz = (z).w - (z).z;                                                \
    float dww = (tid == NTHR - 1) ? 0.f : (zr - (z).w);                       \
    float dhx = (nl) ? ((zN).x - (z).x) : 0.f;                                \
    float dhy = (nl) ? ((zN).y - (z).y) : 0.f;                                \
    float dhz = (nl) ? ((zN).z - (z).z) : 0.f;                                \
    float dhw = (nl) ? ((zN).w - (z).w) : 0.f;                                \
    float v0x = fmaf(SIGMAc, dhx, (u0c).x);                                   \
    float v0y = fmaf(SIGMAc, dhy, (u0c).y);                                   \
    float v0z = fmaf(SIGMAc, dhz, (u0c).z);                                   \
    float v0w = fmaf(SIGMAc, dhw, (u0c).w);                                   \
    float v1x = fmaf(SIGMAc, dwx, (u1c).x);                                   \
    float v1y = fmaf(SIGMAc, dwy, (u1c).y);                                   \
    float v1z = fmaf(SIGMAc, dwz, (u1c).z);                                   \
    float v1w = fmaf(SIGMAc, dww, (u1c).w);                                   \
    float m2x = fmaf(v0x, v0x, v1x * v1x);                                    \
    float m2y = fmaf(v0y, v0y, v1y * v1y);                                    \
    float m2z = fmaf(v0z, v0z, v1z * v1z);                                    \
    float m2w = fmaf(v0w, v0w, v1w * v1w);                                    \
    float scx = (m2x > THS2c) ? (THSc * rsqrtf(m2x)) : 1.f;                   \
    float scy = (m2y > THS2c) ? (THSc * rsqrtf(m2y)) : 1.f;                   \
    float scz = (m2z > THS2c) ? (THSc * rsqrtf(m2z)) : 1.f;                   \
    float scw = (m2w > THS2c) ? (THSc * rsqrtf(m2w)) : 1.f;                   \
    float4 xn, u0n, u1n;                                                      \
    xn.x  = fmaf(HRHOc, (z).x - (x2c).x, (x2c).x);                            \
    xn.y  = fmaf(HRHOc, (z).y - (x2c).y, (x2c).y);                            \
    xn.z  = fmaf(HRHOc, (z).z - (x2c).z, (x2c).z);                            \
    xn.w  = fmaf(HRHOc, (z).w - (x2c).w, (x2c).w);                            \
    u0n.x = fmaf(RHOc, fmaf(v0x, scx, -(u0c).x), (u0c).x);                    \
    u0n.y = fmaf(RHOc, fmaf(v0y, scy, -(u0c).y), (u0c).y);                    \
    u0n.z = fmaf(RHOc, fmaf(v0z, scz, -(u0c).z), (u0c).z);                    \
    u0n.w = fmaf(RHOc, fmaf(v0w, scw, -(u0c).w), (u0c).w);                    \
    u1n.x = fmaf(RHOc, fmaf(v1x, scx, -(u1c).x), (u1c).x);                    \
    u1n.y = fmaf(RHOc, fmaf(v1y, scy, -(u1c).y), (u1c).y);                    \
    u1n.z = fmaf(RHOc, fmaf(v1z, scz, -(u1c).z), (u1c).z);                    \
    u1n.w = fmaf(RHOc, fmaf(v1w, scw, -(u1c).w), (u1c).w);

#define ACCUM_STATS(xn, x2c, num, den)                                        \
    { float d0 = (xn).x - (x2c).x, d1 = (xn).y - (x2c).y;                     \
      float d2 = (xn).z - (x2c).z, d3 = (xn).w - (x2c).w;                     \
      (num) = fmaf(d0, d0, (num));  (num) = fmaf(d1, d1, (num));              \
      (num) = fmaf(d2, d2, (num));  (num) = fmaf(d3, d3, (num));              \
      float e0 = (xn).x + 1e-12f, e1 = (xn).y + 1e-12f;                       \
      float e2 = (xn).z + 1e-12f, e3 = (xn).w + 1e-12f;                       \
      (den) = fmaf(e0, e0, (den));  (den) = fmaf(e1, e1, (den));              \
      (den) = fmaf(e2, e2, (den));  (den) = fmaf(e3, e3, (den)); }

// ---- Phase A: step t over rows [a0, a0+TRIPS), a0 = i0-(isTop?0:1);
//      results -> smem; stats over owned rows only. ----
template<int TRIPS, int NR>
__device__ __forceinline__ void phaseA(
    const float* __restrict__ xin, const float* __restrict__ u0in,
    const float* __restrict__ u1in, const float* __restrict__ yv,
    float* sx2, float* su0, float* su1,
    int g0, int i0, bool isTop, bool notBottom,
    int tid, int lane, bool cfixOK,
    float& num, float& den)
{
    const int c = 4 * tid;
    const float4 zz = make_float4(0.f, 0.f, 0.f, 0.f);
    if (isTop) *(float4*)(su0 + c) = zz;          // slot 0 = u0' of row i0-1

    const int a0  = isTop ? i0 : i0 - 1;
    const int ga0 = isTop ? g0 : g0 - WW;
    const int sb  = isTop ? 1 : 0;                 // slot = r - 1 + sb

    float4 u0prev = isTop ? zz : *(const float4*)(u0in + ga0 - WW);
    float u0fixprev = (cfixOK && !isTop) ? u0in[ga0 + 4 - WW] : 0.f;

    float4 u0c, u1c, x2c, z;
    float zfc, u0fc;
    row_quad(xin, u0in, u1in, yv, ga0, tid, lane, cfixOK, true,
             u0prev, u0fixprev, u0c, u1c, x2c, z, zfc, u0fc);

    int g = ga0;
    #pragma unroll
    for (int r = 0; r < TRIPS; r++) {
        const bool nl = (r < TRIPS - 1) || notBottom;

        float4 u0N = zz, u1N = zz, x2N = zz, zN = zz;
        float zfN = 0.f, u0fN = 0.f;
        if (nl) {
            const bool nlN = (a0 + r + 1) != (HH - 1);
            row_quad(xin, u0in, u1in, yv, g + WW, tid, lane, cfixOK, nlN,
                     u0c, u0fc, u0N, u1N, x2N, zN, zfN, u0fN);
        }

        {
            FINALIZE(z, zN, zfc, u0c, u1c, x2c, nl, xn, u0n, u1n)
            const int slot = r - 1 + sb;
            *(float4*)(su0 + (slot + 1) * WW + c) = u0n;
            if (slot >= 0) {
                *(float4*)(sx2 + slot * WW + c) = xn;
                *(float4*)(su1 + slot * WW + c) = u1n;
            }
            const bool owned = (slot >= 0) && !((r == TRIPS - 1) && notBottom);
            if (owned) ACCUM_STATS(xn, x2c, num, den)
        }

        u0c = u0N; u1c = u1N; x2c = x2N;
        z = zN; zfc = zfN; u0fc = u0fN;
        g += WW;
    }
}

// ---- Phase B: step t+1 over own rows [i0, i0+NR), state from smem. ----
template<int NR>
__device__ __forceinline__ void phaseB(
    const float* sx2, const float* su0, const float* su1,
    const float* __restrict__ yv,
    float* __restrict__ xout, float* __restrict__ u0out,
    float* __restrict__ u1out,
    int g0, int i0, bool notBottom, int tid, int lane, bool cfixOK,
    float& num, float& den)
{
    const int c = 4 * tid;
    const float4 zz = make_float4(0.f, 0.f, 0.f, 0.f);

    float4 u0c, u1c, x2c, z;
    float zfc;
    row_z_s(sx2, su0, su1, yv + g0, 0, c, tid, lane, cfixOK, true,
            u0c, u1c, x2c, z, zfc);

    int g = g0;
    #pragma unroll
    for (int r = 0; r < NR; r++) {
        const bool nl = (r < NR - 1) || notBottom;

        float4 u0N = zz, u1N = zz, x2N = zz, zN = zz;
        float zfN = 0.f;
        if (nl) {
            const bool nlN = (i0 + r + 1) != (HH - 1);
            row_z_s(sx2, su0, su1, yv + g + WW, r + 1, c, tid, lane, cfixOK,
                    nlN, u0N, u1N, x2N, zN, zfN);
        }

        {
            FINALIZE(z, zN, zfc, u0c, u1c, x2c, nl, xn, u0n, u1n)
            *(float4*)(xout  + g) = xn;
            *(float4*)(u0out + g) = u0n;
            *(float4*)(u1out + g) = u1n;
            ACCUM_STATS(xn, x2c, num, den)
        }

        u0c = u0N; u1c = u1N; x2c = x2N;
        z = zN; zfc = zfN;
        g += WW;
    }
}

__global__ void __launch_bounds__(NTHR, 4)
tv_persistent(const float* __restrict__ yv, float* __restrict__ out)
{
    extern __shared__ float dyn_smem[];
    float* sx2 = dyn_smem + SX2_OFF;
    float* su0 = dyn_smem + SU0_OFF;
    float* su1 = dyn_smem + SU1_OFF;

    const int tid  = threadIdx.x;
    const int lane = tid & 31;
    const int wid  = tid >> 5;
    const int blk  = blockIdx.x;
    const bool cfixOK = (lane == 31) && (tid != NTHR - 1);

    const int b = blk / BPI;
    const int s = blk - b * BPI;
    const int nrows = (s < NB7) ? 7 : 6;
    const int i0 = (s < NB7) ? (7 * s) : (7 * NB7 + 6 * (s - NB7));
    const bool isTop     = (s == 0);
    const bool notBottom = (s != BPI - 1);
    const int g0 = b * IMG + i0 * WW + 4 * tid;

    __shared__ float s_red[4][NWARP];
    __shared__ float s_dec[2];

    // ---- init own stripe: x2 = y, u = 0 ----
    {
        int gg = g0;
        const float4 zzi = make_float4(0.f, 0.f, 0.f, 0.f);
        for (int r = 0; r < nrows; r++, gg += WW) {
            *(float4*)(g_x [0] + gg) = *(const float4*)(yv + gg);
            *(float4*)(g_u0[0] + gg) = zzi;
            *(float4*)(g_u1[0] + gg) = zzi;
        }
    }
    grid_barrier();

    int executed = NITERc;
    int fired = 0;
    int wpLast = 0;

    for (int k = 0; k < NSUP; k++) {
        const int rp = k & 1;
        const int wp = rp ^ 1;
        wpLast = wp;

        const float* __restrict__ xin  = g_x [rp];
        const float* __restrict__ u0in = g_u0[rp];
        const float* __restrict__ u1in = g_u1[rp];
        float* __restrict__ xout  = g_x [wp];
        float* __restrict__ u0out = g_u0[wp];
        float* __restrict__ u1out = g_u1[wp];

        float n1 = 0.f, d1 = 0.f, n2 = 0.f, d2 = 0.f;

        if (s == 0) {
            phaseA<8, 7>(xin, u0in, u1in, yv, sx2, su0, su1,
                         g0, i0, true, true, tid, lane, cfixOK, n1, d1);
            __syncthreads();
            phaseB<7>(sx2, su0, su1, yv, xout, u0out, u1out,
                      g0, i0, true, tid, lane, cfixOK, n2, d2);
        } else if (s < NB7) {
            phaseA<9, 7>(xin, u0in, u1in, yv, sx2, su0, su1,
                         g0, i0, false, true, tid, lane, cfixOK, n1, d1);
            __syncthreads();
            phaseB<7>(sx2, su0, su1, yv, xout, u0out, u1out,
                      g0, i0, true, tid, lane, cfixOK, n2, d2);
        } else if (s < BPI - 1) {
            phaseA<8, 6>(xin, u0in, u1in, yv, sx2, su0, su1,
                         g0, i0, false, true, tid, lane, cfixOK, n1, d1);
            __syncthreads();
            phaseB<6>(sx2, su0, su1, yv, xout, u0out, u1out,
                      g0, i0, true, tid, lane, cfixOK, n2, d2);
        } else {
            phaseA<7, 6>(xin, u0in, u1in, yv, sx2, su0, su1,
                         g0, i0, false, false, tid, lane, cfixOK, n1, d1);
            __syncthreads();
            phaseB<6>(sx2, su0, su1, yv, xout, u0out, u1out,
                      g0, i0, false, tid, lane, cfixOK, n2, d2);
        }

        // -- publish both steps' partials (decisions possible from k >= 1) --
        if (k >= 1) {
            #pragma unroll
            for (int o = 16; o; o >>= 1) {
                n1 += __shfl_down_sync(0xffffffffu, n1, o);
                d1 += __shfl_down_sync(0xffffffffu, d1, o);
                n2 += __shfl_down_sync(0xffffffffu, n2, o);
                d2 += __shfl_down_sync(0xffffffffu, d2, o);
            }
            if (lane == 0) {
                s_red[0][wid] = n1; s_red[1][wid] = d1;
                s_red[2][wid] = n2; s_red[3][wid] = d2;
            }
            __syncthreads();
            if (tid == 0) {
                float a0v = 0.f, a1v = 0.f, a2v = 0.f, a3v = 0.f;
                #pragma unroll
                for (int w = 0; w < NWARP; w++) {
                    a0v += s_red[0][w]; a1v += s_red[1][w];
                    a2v += s_red[2][w]; a3v += s_red[3][w];
                }
                g_pn1[rp][blk] = a0v; g_pd1[rp][blk] = a1v;
                g_pn2[rp][blk] = a2v; g_pd2[rp][blk] = a3v;
            }
        }

        grid_barrier();

        if (k >= 1) {
            // redundant fixed-order reduce of all 592 partials (deterministic)
            float b0 = 0.f, b1 = 0.f, b2 = 0.f, b3 = 0.f;
            #pragma unroll
            for (int m = 0; m < (NBLK + NTHR - 1) / NTHR; m++) {
                int idx = tid + m * NTHR;
                if (idx < NBLK) {
                    b0 += g_pn1[rp][idx]; b1 += g_pd1[rp][idx];
                    b2 += g_pn2[rp][idx]; b3 += g_pd2[rp][idx];
                }
            }
            #pragma unroll
            for (int o = 16; o; o >>= 1) {
                b0 += __shfl_down_sync(0xffffffffu, b0, o);
                b1 += __shfl_down_sync(0xffffffffu, b1, o);
                b2 += __shfl_down_sync(0xffffffffu, b2, o);
                b3 += __shfl_down_sync(0xffffffffu, b3, o);
            }
            if (lane == 0) {
                s_red[0][wid] = b0; s_red[1][wid] = b1;
                s_red[2][wid] = b2; s_red[3][wid] = b3;
            }
            __syncthreads();
            if (tid == 0) {
                float N1 = 0.f, D1 = 0.f, N2 = 0.f, D2 = 0.f;
                #pragma unroll
                for (int w = 0; w < NWARP; w++) {
                    N1 += s_red[0][w]; D1 += s_red[1][w];
                    N2 += s_red[2][w]; D2 += s_red[3][w];
                }
                s_dec[0] = sqrtf(N1) / sqrtf(D1);
                s_dec[1] = sqrtf(N2) / sqrtf(D2);
            }
            __syncthreads();
            if (s_dec[0] < CRITc) { fired = 1; executed = 2 * k + 1; break; }
            if (s_dec[1] < CRITc) { fired = 2; executed = 2 * k + 2; break; }
            __syncthreads();   // protect s_red/s_dec reuse next superstep
        }
    }
    (void)executed;

    // ---- write output ----
    if (fired == 1) {
        // result is the step-(2k+1) state, still in smem (phase B didn't touch it)
        int gg = g0;
        for (int r = 0; r < nrows; r++, gg += WW)
            *(float4*)(out + gg) = *(const float4*)(sx2 + r * WW + 4 * tid);
    } else {
        const float* __restrict__ src = g_x[wpLast];
        int gg = g0;
        for (int r = 0; r < nrows; r++, gg += WW)
            *(float4*)(out + gg) = *(const float4*)(src + gg);
    }
}

extern "C" void kernel_launch(void* const* d_in, const int* in_sizes, int n_in,
                              void* d_out, int out_size) {
    const float* y = (const float*)d_in[0];
    float* out = (float*)d_out;
    const int smem_bytes = SMEM_FLOATS * sizeof(float);   // 51200 B dynamic
    cudaFuncSetAttribute(tv_persistent,
                         cudaFuncAttributeMaxDynamicSharedMemorySize,
                         smem_bytes + 1024);
    tv_persistent<<<NBLK, NTHR, smem_bytes>>>(y, out);
}

// round 14
// speedup vs baseline: 1.3859x; 1.0214x over previous
#include <cuda_runtime.h>

// Persistent-kernel TV denoiser (Chambolle-Pock, RHO-relaxed), single launch.
// TEMPORAL BLOCKING: 2 iterations per grid barrier. Phase A computes step t
// for the stripe +1 halo row each side (reads global parity p) into SMEM;
// Phase B computes step t+1 from SMEM and writes global parity p^1.
// 592 blocks (=148 SMs x 4 CTAs) x 256 threads, float2 columns (32 warps/SM).

#define WW 512
#define HH 512
#define IMG (HH*WW)
#define BATCH 8
#define NTOT (BATCH*IMG)
#define NTHR 256
#define NWARP (NTHR/32)
#define BPI 74                   // blocks per image
#define NBLK (BATCH*BPI)         // 592 = 148*4, all co-resident
#define NB7 68                   // stripes 0..67: 7 rows; 68..73: 6 rows
#define NSUP 20                  // supersteps (2 iters each)

#define TAUc     0.01f
#define INV1PTAU (1.0f/1.01f)
#define SIGMAc   12.5f
#define RHOc     1.99f
#define HRHOc    0.995f
#define THSc     0.1f
#define THS2c    0.01f
#define CRITc    1e-5f
#define NITERc   40

// smem layout (rows of WW floats): sx2: 8 rows, su0: 9 rows, su1: 8 rows
#define SX2_OFF 0
#define SU0_OFF (8*WW)
#define SU1_OFF (17*WW)
#define SMEM_FLOATS (25*WW)      // 51200 B

__device__ float g_x [2][NTOT];
__device__ float g_u0[2][NTOT];
__device__ float g_u1[2][NTOT];
__device__ float g_pn1[2][NBLK], g_pd1[2][NBLK];
__device__ float g_pn2[2][NBLK], g_pd2[2][NBLK];
__device__ unsigned int          g_count = 0;
__device__ volatile unsigned int g_gen   = 0;

__device__ __forceinline__ void grid_barrier()
{
    __threadfence();
    __syncthreads();
    if (threadIdx.x == 0) {
        unsigned int gen = g_gen;
        if (atomicInc(&g_count, NBLK - 1u) == NBLK - 1u) {
            g_gen = gen + 1u;
        } else {
            while (g_gen == gen) __nanosleep(32);
        }
    }
    __syncthreads();
    __threadfence();
}

// ---- z from GLOBAL state (float2), lane-31 fixup column c+2 ----
__device__ __forceinline__ void row2_g(
    const float* __restrict__ xin, const float* __restrict__ u0in,
    const float* __restrict__ u1in, const float* __restrict__ yv,
    int g, int tid, int lane, bool cfixOK, bool nl,
    float2 u0prev, float u0fixprev,
    float2& u0c, float2& u1c, float2& x2c,
    float& z0, float& z1, float& zf, float& u0fc)
{
    u0c = *(const float2*)(u0in + g);
    u1c = *(const float2*)(u1in + g);
    x2c = *(const float2*)(xin  + g);
    float2 yc = *(const float2*)(yv + g);

    float u1left = __shfl_up_sync(0xffffffffu, u1c.y, 1);
    if (lane == 0) u1left = (tid > 0) ? u1in[g - 1] : 0.f;

    float u0x = nl ? u0c.x : 0.f;
    float u0y = nl ? u0c.y : 0.f;
    float u1y = (tid == NTHR - 1) ? 0.f : u1c.y;   // col 511: no right diff

    float a0 = u0prev.x + u1left - u0x - u1c.x;
    float a1 = u0prev.y + u1c.x  - u0y - u1y;

    float x0 = fmaf(TAUc, yc.x - a0, x2c.x) * INV1PTAU;
    float x1 = fmaf(TAUc, yc.y - a1, x2c.y) * INV1PTAU;
    z0 = 2.f * x0 - x2c.x;
    z1 = 2.f * x1 - x2c.y;

    zf = 0.f; u0fc = 0.f;
    if (cfixOK) {                       // lane 31 (not tid 255): column c+2
        float u0f = u0in[g + 2];
        float u1f = u1in[g + 2];
        float x2f = xin [g + 2];
        float yf  = yv  [g + 2];
        float u0fx = nl ? u0f : 0.f;
        float af = u0fixprev + u1c.y - u0fx - u1f;
        float xf = fmaf(TAUc, yf - af, x2f) * INV1PTAU;
        zf = 2.f * xf - x2f;
        u0fc = u0f;
    }
}

// ---- z from SMEM state (float2). su0 slot k = image row i0+k-1. ----
__device__ __forceinline__ void row2_s(
    const float* sx2, const float* su0, const float* su1,
    const float* __restrict__ yg,
    int rr, int c, int tid, int lane, bool cfixOK, bool nl,
    float2& u0c, float2& u1c, float2& x2c, float& z0, float& z1, float& zf)
{
    u0c = *(const float2*)(su0 + (rr + 1) * WW + c);
    u1c = *(const float2*)(su1 + rr * WW + c);
    x2c = *(const float2*)(sx2 + rr * WW + c);
    float2 u0p = *(const float2*)(su0 + rr * WW + c);
    float2 yc  = *(const float2*)(yg);

    float u1left = __shfl_up_sync(0xffffffffu, u1c.y, 1);
    if (lane == 0) u1left = (tid > 0) ? su1[rr * WW + c - 1] : 0.f;

    float u0x = nl ? u0c.x : 0.f;
    float u0y = nl ? u0c.y : 0.f;
    float u1y = (tid == NTHR - 1) ? 0.f : u1c.y;

    float a0 = u0p.x + u1left - u0x - u1c.x;
    float a1 = u0p.y + u1c.x  - u0y - u1y;

    float x0 = fmaf(TAUc, yc.x - a0, x2c.x) * INV1PTAU;
    float x1 = fmaf(TAUc, yc.y - a1, x2c.y) * INV1PTAU;
    z0 = 2.f * x0 - x2c.x;
    z1 = 2.f * x1 - x2c.y;

    zf = 0.f;
    if (cfixOK) {
        float u0f  = su0[(rr + 1) * WW + c + 2];
        float u0pf = su0[rr * WW + c + 2];
        float u1f  = su1[rr * WW + c + 2];
        float x2f  = sx2[rr * WW + c + 2];
        float yf   = yg[2];
        float u0fx = nl ? u0f : 0.f;
        float af = u0pf + u1c.y - u0fx - u1f;
        float xf = fmaf(TAUc, yf - af, x2f) * INV1PTAU;
        zf = 2.f * xf - x2f;
    }
}

// prox + relax (float2) -> xn, u0n, u1n
#define FINALIZE2(z0v, z1v, zN0, zN1, zfc, u0c, u1c, x2c, nl, xn, u0n, u1n)   \
    float zsh = __shfl_down_sync(0xffffffffu, (z0v), 1);                      \
    float zr  = (lane == 31) ? (zfc) : zsh;                                   \
    float dw0 = (z1v) - (z0v);                                                \
    float dw1 = (tid == NTHR - 1) ? 0.f : (zr - (z1v));                       \
    float dh0 = (nl) ? ((zN0) - (z0v)) : 0.f;                                 \
    float dh1 = (nl) ? ((zN1) - (z1v)) : 0.f;                                 \
    float v00 = fmaf(SIGMAc, dh0, (u0c).x);                                   \
    float v01 = fmaf(SIGMAc, dh1, (u0c).y);                                   \
    float v10 = fmaf(SIGMAc, dw0, (u1c).x);                                   \
    float v11 = fmaf(SIGMAc, dw1, (u1c).y);                                   \
    float m20 = fmaf(v00, v00, v10 * v10);                                    \
    float m21 = fmaf(v01, v01, v11 * v11);                                    \
    float sc0 = (m20 > THS2c) ? (THSc * rsqrtf(m20)) : 1.f;                   \
    float sc1 = (m21 > THS2c) ? (THSc * rsqrtf(m21)) : 1.f;                   \
    float2 xn, u0n, u1n;                                                      \
    xn.x  = fmaf(HRHOc, (z0v) - (x2c).x, (x2c).x);                            \
    xn.y  = fmaf(HRHOc, (z1v) - (x2c).y, (x2c).y);                            \
    u0n.x = fmaf(RHOc, fmaf(v00, sc0, -(u0c).x), (u0c).x);                    \
    u0n.y = fmaf(RHOc, fmaf(v01, sc1, -(u0c).y), (u0c).y);                    \
    u1n.x = fmaf(RHOc, fmaf(v10, sc0, -(u1c).x), (u1c).x);                    \
    u1n.y = fmaf(RHOc, fmaf(v11, sc1, -(u1c).y), (u1c).y);

#define ACCUM2(xn, x2c, num, den)                                             \
    { float d0 = (xn).x - (x2c).x, d1 = (xn).y - (x2c).y;                     \
      (num) = fmaf(d0, d0, (num));  (num) = fmaf(d1, d1, (num));              \
      float e0 = (xn).x + 1e-12f, e1 = (xn).y + 1e-12f;                       \
      (den) = fmaf(e0, e0, (den));  (den) = fmaf(e1, e1, (den)); }

// ---- Phase A: step t over rows [a0, a0+TRIPS) -> smem; stats on owned. ----
template<int TRIPS>
__device__ __forceinline__ void phaseA(
    const float* __restrict__ xin, const float* __restrict__ u0in,
    const float* __restrict__ u1in, const float* __restrict__ yv,
    float* sx2, float* su0, float* su1,
    int g0, int i0, bool isTop, bool notBottom,
    int tid, int lane, bool cfixOK,
    float& num, float& den)
{
    const int c = 2 * tid;
    const float2 zz = make_float2(0.f, 0.f);
    if (isTop) *(float2*)(su0 + c) = zz;          // slot 0 = u0' of row i0-1

    const int a0  = isTop ? i0 : i0 - 1;
    const int ga0 = isTop ? g0 : g0 - WW;
    const int sb  = isTop ? 1 : 0;                 // slot = r - 1 + sb

    float2 u0prev = isTop ? zz : *(const float2*)(u0in + ga0 - WW);
    float u0fixprev = (cfixOK && !isTop) ? u0in[ga0 + 2 - WW] : 0.f;

    float2 u0c, u1c, x2c;
    float z0, z1, zfc, u0fc;
    row2_g(xin, u0in, u1in, yv, ga0, tid, lane, cfixOK, true,
           u0prev, u0fixprev, u0c, u1c, x2c, z0, z1, zfc, u0fc);

    int g = ga0;
    #pragma unroll
    for (int r = 0; r < TRIPS; r++) {
        const bool nl = (r < TRIPS - 1) || notBottom;

        float2 u0N = zz, u1N = zz, x2N = zz;
        float zN0 = 0.f, zN1 = 0.f, zfN = 0.f, u0fN = 0.f;
        if (nl) {
            const bool nlN = (a0 + r + 1) != (HH - 1);
            row2_g(xin, u0in, u1in, yv, g + WW, tid, lane, cfixOK, nlN,
                   u0c, u0fc, u0N, u1N, x2N, zN0, zN1, zfN, u0fN);
        }

        {
            FINALIZE2(z0, z1, zN0, zN1, zfc, u0c, u1c, x2c, nl, xn, u0n, u1n)
            const int slot = r - 1 + sb;
            *(float2*)(su0 + (slot + 1) * WW + c) = u0n;
            if (slot >= 0) {
                *(float2*)(sx2 + slot * WW + c) = xn;
                *(float2*)(su1 + slot * WW + c) = u1n;
            }
            const bool owned = (slot >= 0) && !((r == TRIPS - 1) && notBottom);
            if (owned) ACCUM2(xn, x2c, num, den)
        }

        u0c = u0N; u1c = u1N; x2c = x2N;
        z0 = zN0; z1 = zN1; zfc = zfN; u0fc = u0fN;
        g += WW;
    }
}

// ---- Phase B: step t+1 over own rows [i0, i0+NR), state from smem. ----
template<int NR>
__device__ __forceinline__ void phaseB(
    const float* sx2, const float* su0, const float* su1,
    const float* __restrict__ yv,
    float* __restrict__ xout, float* __restrict__ u0out,
    float* __restrict__ u1out,
    int g0, int i0, bool notBottom, int tid, int lane, bool cfixOK,
    float& num, float& den)
{
    const int c = 2 * tid;
    const float2 zz = make_float2(0.f, 0.f);

    float2 u0c, u1c, x2c;
    float z0, z1, zfc;
    row2_s(sx2, su0, su1, yv + g0, 0, c, tid, lane, cfixOK, true,
           u0c, u1c, x2c, z0, z1, zfc);

    int g = g0;
    #pragma unroll
    for (int r = 0; r < NR; r++) {
        const bool nl = (r < NR - 1) || notBottom;

        float2 u0N = zz, u1N = zz, x2N = zz;
        float zN0 = 0.f, zN1 = 0.f, zfN = 0.f;
        if (nl) {
            const bool nlN = (i0 + r + 1) != (HH - 1);
            row2_s(sx2, su0, su1, yv + g + WW, r + 1, c, tid, lane, cfixOK,
                   nlN, u0N, u1N, x2N, zN0, zN1, zfN);
        }

        {
            FINALIZE2(z0, z1, zN0, zN1, zfc, u0c, u1c, x2c, nl, xn, u0n, u1n)
            *(float2*)(xout  + g) = xn;
            *(float2*)(u0out + g) = u0n;
            *(float2*)(u1out + g) = u1n;
            ACCUM2(xn, x2c, num, den)
        }

        u0c = u0N; u1c = u1N; x2c = x2N;
        z0 = zN0; z1 = zN1; zfc = zfN;
        g += WW;
    }
}

__global__ void __launch_bounds__(NTHR, 4)
tv_persistent(const float* __restrict__ yv, float* __restrict__ out)
{
    extern __shared__ float dyn_smem[];
    float* sx2 = dyn_smem + SX2_OFF;
    float* su0 = dyn_smem + SU0_OFF;
    float* su1 = dyn_smem + SU1_OFF;

    const int tid  = threadIdx.x;
    const int lane = tid & 31;
    const int wid  = tid >> 5;
    const int blk  = blockIdx.x;
    const bool cfixOK = (lane == 31) && (tid != NTHR - 1);

    const int b = blk / BPI;
    const int s = blk - b * BPI;
    const int nrows = (s < NB7) ? 7 : 6;
    const int i0 = (s < NB7) ? (7 * s) : (7 * NB7 + 6 * (s - NB7));
    const bool notBottom = (s != BPI - 1);
    const int g0 = b * IMG + i0 * WW + 2 * tid;

    __shared__ float s_red[4][NWARP];
    __shared__ float s_dec[2];

    // ---- init own stripe: x2 = y, u = 0 ----
    {
        int gg = g0;
        const float2 zzi = make_float2(0.f, 0.f);
        for (int r = 0; r < nrows; r++, gg += WW) {
            *(float2*)(g_x [0] + gg) = *(const float2*)(yv + gg);
            *(float2*)(g_u0[0] + gg) = zzi;
            *(float2*)(g_u1[0] + gg) = zzi;
        }
    }
    grid_barrier();

    int executed = NITERc;
    int fired = 0;
    int wpLast = 0;

    for (int k = 0; k < NSUP; k++) {
        const int rp = k & 1;
        const int wp = rp ^ 1;
        wpLast = wp;

        const float* __restrict__ xin  = g_x [rp];
        const float* __restrict__ u0in = g_u0[rp];
        const float* __restrict__ u1in = g_u1[rp];
        float* __restrict__ xout  = g_x [wp];
        float* __restrict__ u0out = g_u0[wp];
        float* __restrict__ u1out = g_u1[wp];

        float n1 = 0.f, d1 = 0.f, n2 = 0.f, d2 = 0.f;

        if (s == 0) {
            phaseA<8>(xin, u0in, u1in, yv, sx2, su0, su1,
                      g0, i0, true, true, tid, lane, cfixOK, n1, d1);
            __syncthreads();
            phaseB<7>(sx2, su0, su1, yv, xout, u0out, u1out,
                      g0, i0, true, tid, lane, cfixOK, n2, d2);
        } else if (s < NB7) {
            phaseA<9>(xin, u0in, u1in, yv, sx2, su0, su1,
                      g0, i0, false, true, tid, lane, cfixOK, n1, d1);
            __syncthreads();
            phaseB<7>(sx2, su0, su1, yv, xout, u0out, u1out,
                      g0, i0, true, tid, lane, cfixOK, n2, d2);
        } else if (s < BPI - 1) {
            phaseA<8>(xin, u0in, u1in, yv, sx2, su0, su1,
                      g0, i0, false, true, tid, lane, cfixOK, n1, d1);
            __syncthreads();
            phaseB<6>(sx2, su0, su1, yv, xout, u0out, u1out,
                      g0, i0, true, tid, lane, cfixOK, n2, d2);
        } else {
            phaseA<7>(xin, u0in, u1in, yv, sx2, su0, su1,
                      g0, i0, false, false, tid, lane, cfixOK, n1, d1);
            __syncthreads();
            phaseB<6>(sx2, su0, su1, yv, xout, u0out, u1out,
                      g0, i0, false, tid, lane, cfixOK, n2, d2);
        }

        // -- publish both steps' partials (decisions possible from k >= 1) --
        if (k >= 1) {
            #pragma unroll
            for (int o = 16; o; o >>= 1) {
                n1 += __shfl_down_sync(0xffffffffu, n1, o);
                d1 += __shfl_down_sync(0xffffffffu, d1, o);
                n2 += __shfl_down_sync(0xffffffffu, n2, o);
                d2 += __shfl_down_sync(0xffffffffu, d2, o);
            }
            if (lane == 0) {
                s_red[0][wid] = n1; s_red[1][wid] = d1;
                s_red[2][wid] = n2; s_red[3][wid] = d2;
            }
            __syncthreads();
            if (tid == 0) {
                float a0v = 0.f, a1v = 0.f, a2v = 0.f, a3v = 0.f;
                #pragma unroll
                for (int w = 0; w < NWARP; w++) {
                    a0v += s_red[0][w]; a1v += s_red[1][w];
                    a2v += s_red[2][w]; a3v += s_red[3][w];
                }
                g_pn1[rp][blk] = a0v; g_pd1[rp][blk] = a1v;
                g_pn2[rp][blk] = a2v; g_pd2[rp][blk] = a3v;
            }
        }

        grid_barrier();

        if (k >= 1) {
            // redundant fixed-order reduce of all 592 partials (deterministic)
            float b0 = 0.f, b1 = 0.f, b2 = 0.f, b3 = 0.f;
            #pragma unroll
            for (int m = 0; m < (NBLK + NTHR - 1) / NTHR; m++) {
                int idx = tid + m * NTHR;
                if (idx < NBLK) {
                    b0 += g_pn1[rp][idx]; b1 += g_pd1[rp][idx];
                    b2 += g_pn2[rp][idx]; b3 += g_pd2[rp][idx];
                }
            }
            #pragma unroll
            for (int o = 16; o; o >>= 1) {
                b0 += __shfl_down_sync(0xffffffffu, b0, o);
                b1 += __shfl_down_sync(0xffffffffu, b1, o);
                b2 += __shfl_down_sync(0xffffffffu, b2, o);
                b3 += __shfl_down_sync(0xffffffffu, b3, o);
            }
            if (lane == 0) {
                s_red[0][wid] = b0; s_red[1][wid] = b1;
                s_red[2][wid] = b2; s_red[3][wid] = b3;
            }
            __syncthreads();
            if (tid == 0) {
                float N1 = 0.f, D1 = 0.f, N2 = 0.f, D2 = 0.f;
                #pragma unroll
                for (int w = 0; w < NWARP; w++) {
                    N1 += s_red[0][w]; D1 += s_red[1][w];
                    N2 += s_red[2][w]; D2 += s_red[3][w];
                }
                s_dec[0] = sqrtf(N1) / sqrtf(D1);
                s_dec[1] = sqrtf(N2) / sqrtf(D2);
            }
            __syncthreads();
            if (s_dec[0] < CRITc) { fired = 1; executed = 2 * k + 1; break; }
            if (s_dec[1] < CRITc) { fired = 2; executed = 2 * k + 2; break; }
            __syncthreads();   // protect s_red/s_dec reuse next superstep
        }
    }
    (void)executed;

    // ---- write output ----
    if (fired == 1) {
        // result = step-(2k+1) state, still intact in smem
        int gg = g0;
        for (int r = 0; r < nrows; r++, gg += WW)
            *(float2*)(out + gg) = *(const float2*)(sx2 + r * WW + 2 * tid);
    } else {
        const float* __restrict__ src = g_x[wpLast];
        int gg = g0;
        for (int r = 0; r < nrows; r++, gg += WW)
            *(float2*)(out + gg) = *(const float2*)(src + gg);
    }
}

extern "C" void kernel_launch(void* const* d_in, const int* in_sizes, int n_in,
                              void* d_out, int out_size) {
    const float* y = (const float*)d_in[0];
    float* out = (float*)d_out;
    const int smem_bytes = SMEM_FLOATS * sizeof(float);   // 51200 B dynamic
    cudaFuncSetAttribute(tv_persistent,
                         cudaFuncAttributeMaxDynamicSharedMemorySize,
                         smem_bytes + 1024);
    tv_persistent<<<NBLK, NTHR, smem_bytes>>>(y, out);
}